// round 10
// baseline (speedup 1.0000x reference)
#include <cuda_runtime.h>
#include <cuda_fp16.h>
#include <mma.h>
#include <cstdint>
using namespace nvcuda;

#define NNODES 50000
#define NPAD   50048
#define NREL   3
#define NEDGE  600000
#define E4     (NEDGE / 4)          // 150000
#define FIN1   128
#define FHID   64

// ---------------- scratch (no allocs allowed) ----------------
__device__ __align__(128) __half g_xh[(size_t)NPAD * FIN1];
__device__ __align__(128) __half g_w1h[NREL * FIN1 * FHID];
__device__ __align__(128) __half g_w2h[NREL * FHID * FHID];
__device__ __align__(128) __half g_H[(size_t)NREL * NPAD * FHID];
__device__ __align__(128) __half g_h1h[(size_t)NPAD * FHID];
__device__ int g_odeg[NREL * NNODES];
__device__ int g_ideg[NREL * NNODES];
__device__ int g_off[NNODES + 1];    // merged per-node CSR offsets
__device__ int g_cursor[NNODES];
__device__ int g_eidx[NREL * NEDGE]; // packed: (r<<20) | (r*NPAD + src)
__device__ int g_bsum[64];

// ---------------- init: zero degree counters + h1 pad rows ----------------
__global__ void init_kernel() {
    int i = blockIdx.x * blockDim.x + threadIdx.x;
    if (i < NREL * NNODES) { g_odeg[i] = 0; g_ideg[i] = 0; }
    if (i < (NPAD - NNODES) * 32)
        ((__half2*)g_h1h)[(size_t)NNODES * 32 + i] = __floats2half2_rn(0.f, 0.f);
}

// ---------------- fused: degree histograms (int4) + fp16 converts ----------
#define DEG_B   ((NREL * E4 + 255) / 256)                    // 1758
#define CONVX_B ((NPAD * (FIN1 / 8) + 255) / 256)            // 3128
#define CONVW_B ((NREL * (FIN1 + FHID) * FHID + 255) / 256)  // 144

__global__ void degconv_kernel(const float* __restrict__ x,
                               const float* __restrict__ W1, const float* __restrict__ W2,
                               const int* __restrict__ src, const int* __restrict__ dst) {
    int b = blockIdx.x;
    if (b < DEG_B) {
        int t = b * 256 + threadIdx.x;
        if (t >= NREL * E4) return;
        int r = t / E4;
        int i = t - r * E4;
        int4 s4 = ((const int4*)(src + (size_t)r * NEDGE))[i];
        int4 d4 = ((const int4*)(dst + (size_t)r * NEDGE))[i];
        int rb = r * NNODES;
        atomicAdd(&g_odeg[rb + s4.x], 1);
        atomicAdd(&g_odeg[rb + s4.y], 1);
        atomicAdd(&g_odeg[rb + s4.z], 1);
        atomicAdd(&g_odeg[rb + s4.w], 1);
        atomicAdd(&g_ideg[rb + d4.x], 1);
        atomicAdd(&g_ideg[rb + d4.y], 1);
        atomicAdd(&g_ideg[rb + d4.z], 1);
        atomicAdd(&g_ideg[rb + d4.w], 1);
    } else if (b < DEG_B + CONVX_B) {
        int i = (b - DEG_B) * 256 + threadIdx.x;
        if (i >= NPAD * (FIN1 / 8)) return;
        size_t gi = (size_t)i * 8;
        int row = (int)(gi >> 7);
        union { uint4 u; __half2 h[4]; } p;
        if (row < NNODES) {
            float4 a = *(const float4*)(x + gi);
            float4 c = *(const float4*)(x + gi + 4);
            p.h[0] = __floats2half2_rn(a.x, a.y);
            p.h[1] = __floats2half2_rn(a.z, a.w);
            p.h[2] = __floats2half2_rn(c.x, c.y);
            p.h[3] = __floats2half2_rn(c.z, c.w);
        } else {
            p.h[0] = p.h[1] = p.h[2] = p.h[3] = __floats2half2_rn(0.f, 0.f);
        }
        *(uint4*)(g_xh + gi) = p.u;
    } else {
        int i = (b - DEG_B - CONVX_B) * 256 + threadIdx.x;
        const int T1 = NREL * FIN1 * FHID;
        const int T2 = NREL * FHID * FHID;
        if (i < T1) g_w1h[i] = __float2half_rn(W1[i]);
        else if (i < T1 + T2) g_w2h[i - T1] = __float2half_rn(W2[i - T1]);
    }
}

// ---------------- scan phase 1: per-1024 block scan of merged in-degree -----
__global__ void scan1_kernel(int N) {
    __shared__ int sh[256];
    int t = threadIdx.x;
    int base = blockIdx.x * 1024 + t * 4;
    int v[4];
    #pragma unroll
    for (int j = 0; j < 4; j++) {
        int n = base + j;
        v[j] = (n < N) ? (g_ideg[n] + g_ideg[N + n] + g_ideg[2 * N + n]) : 0;
    }
    int t0 = v[0], t1 = t0 + v[1], t2 = t1 + v[2], t3 = t2 + v[3];
    sh[t] = t3;
    __syncthreads();
    for (int off = 1; off < 256; off <<= 1) {
        int x = (t >= off) ? sh[t - off] : 0;
        __syncthreads();
        sh[t] += x;
        __syncthreads();
    }
    int excl = (t > 0) ? sh[t - 1] : 0;
    if (base + 0 < N) g_off[base + 0] = excl;
    if (base + 1 < N) g_off[base + 1] = excl + t0;
    if (base + 2 < N) g_off[base + 2] = excl + t1;
    if (base + 3 < N) g_off[base + 3] = excl + t2;
    if (t == 255) g_bsum[blockIdx.x] = sh[255];
}

// ---------------- scan phase 2+3 merged: every block re-scans 49 sums -------
__global__ void scan23_kernel(int N, int totalE, int scanB) {
    __shared__ int sb[64];
    int t = threadIdx.x;
    if (t < 64) sb[t] = (t < scanB) ? g_bsum[t] : 0;
    __syncthreads();
    for (int off = 1; off < 64; off <<= 1) {
        int x = (t < 64 && t >= off) ? sb[t - off] : 0;
        __syncthreads();
        if (t < 64) sb[t] += x;
        __syncthreads();
    }
    int i = blockIdx.x * 256 + t;
    if (i < N) {
        int blk = i >> 10;
        int v = g_off[i] + (blk ? sb[blk - 1] : 0);
        g_off[i] = v;
        g_cursor[i] = v;
    }
    if (i == 0) g_off[N] = totalE;
}

// ---------------- fill merged CSR (int4, packed relation tag) ---------------
__global__ void fill_kernel(const int* __restrict__ src, const int* __restrict__ dst) {
    int t = blockIdx.x * 256 + threadIdx.x;
    if (t >= NREL * E4) return;
    int r = t / E4;
    int i = t - r * E4;
    int4 s4 = ((const int4*)(src + (size_t)r * NEDGE))[i];
    int4 d4 = ((const int4*)(dst + (size_t)r * NEDGE))[i];
    int tag = (r << 20) + r * NPAD;
    int p0 = atomicAdd(&g_cursor[d4.x], 1);
    int p1 = atomicAdd(&g_cursor[d4.y], 1);
    int p2 = atomicAdd(&g_cursor[d4.z], 1);
    int p3 = atomicAdd(&g_cursor[d4.w], 1);
    g_eidx[p0] = tag + s4.x;
    g_eidx[p1] = tag + s4.y;
    g_eidx[p2] = tag + s4.z;
    g_eidx[p3] = tag + s4.w;
}

// ---------------- tensor-core GEMM: H[r][row] = fp16(rsqrt(odeg)*(X@W[r])) ---
template <int K>
__global__ void gemm_tc(const __half* __restrict__ Xh, const __half* __restrict__ Wh,
                        __half* __restrict__ Hout, int N) {
    __shared__ float sC[32 * 72];
    const int r    = blockIdx.y;
    const int row0 = blockIdx.x * 32;
    const int wid  = threadIdx.x >> 5;
    const int msub = wid >> 2, nsub = wid & 3;

    wmma::fragment<wmma::accumulator, 16, 16, 16, float> c;
    wmma::fill_fragment(c, 0.0f);
    const __half* A = Xh + (size_t)(row0 + msub * 16) * K;
    const __half* B = Wh + (size_t)r * K * 64 + nsub * 16;
    #pragma unroll
    for (int k0 = 0; k0 < K; k0 += 16) {
        wmma::fragment<wmma::matrix_a, 16, 16, 16, __half, wmma::row_major> a;
        wmma::fragment<wmma::matrix_b, 16, 16, 16, __half, wmma::row_major> b;
        wmma::load_matrix_sync(a, A + k0, K);
        wmma::load_matrix_sync(b, B + (size_t)k0 * 64, 64);
        wmma::mma_sync(c, a, b, c);
    }
    wmma::store_matrix_sync(sC + msub * 16 * 72 + nsub * 16, c, 72, wmma::mem_row_major);
    __syncthreads();

    #pragma unroll
    for (int i = threadIdx.x; i < 32 * 32; i += 256) {
        int row = i >> 5, c2 = i & 31;
        int grow = row0 + row;
        if (grow < N) {
            int od = g_odeg[r * N + grow];
            float s = rsqrtf((float)(od < 1 ? 1 : od));
            float v0 = sC[row * 72 + c2 * 2];
            float v1 = sC[row * 72 + c2 * 2 + 1];
            ((__half2*)Hout)[((size_t)r * NPAD + grow) * 32 + c2] =
                __floats2half2_rn(v0 * s, v1 * s);
        }
    }
}

// ---------------- gather over merged CSR, fused norm+bias+relu --------------
// one warp per node; lane owns 2 channels. per-edge relation tag selects norm.
template <bool HALF_OUT>
__global__ void gather_kernel(const __half* __restrict__ H, const float* __restrict__ bias,
                              void* __restrict__ outp, int N) {
    int warp = (blockIdx.x * blockDim.x + threadIdx.x) >> 5;
    int lane = threadIdx.x & 31;
    if (warp >= N) return;
    const int n = warp;

    int d0 = g_ideg[n], d1 = g_ideg[N + n], d2 = g_ideg[2 * N + n];
    float n0 = rsqrtf((float)(d0 < 1 ? 1 : d0));
    float n1 = rsqrtf((float)(d1 < 1 ? 1 : d1));
    float n2 = rsqrtf((float)(d2 < 1 ? 1 : d2));

    const __half2* H2 = (const __half2*)H + lane;
    int beg = g_off[n];
    int end = g_off[n + 1];

    float sx = 0.f, sy = 0.f;
    for (int base = beg; base < end; base += 32) {
        int m = end - base; if (m > 32) m = 32;
        int myid = (lane < m) ? g_eidx[base + lane] : 0;
        int j = 0;
        for (; j + 8 <= m; j += 8) {
            int p0 = __shfl_sync(0xffffffffu, myid, j);
            int p1 = __shfl_sync(0xffffffffu, myid, j + 1);
            int p2 = __shfl_sync(0xffffffffu, myid, j + 2);
            int p3 = __shfl_sync(0xffffffffu, myid, j + 3);
            int p4 = __shfl_sync(0xffffffffu, myid, j + 4);
            int p5 = __shfl_sync(0xffffffffu, myid, j + 5);
            int p6 = __shfl_sync(0xffffffffu, myid, j + 6);
            int p7 = __shfl_sync(0xffffffffu, myid, j + 7);
            float2 v0 = __half22float2(H2[(size_t)(p0 & 0xFFFFF) * 32]);
            float2 v1 = __half22float2(H2[(size_t)(p1 & 0xFFFFF) * 32]);
            float2 v2 = __half22float2(H2[(size_t)(p2 & 0xFFFFF) * 32]);
            float2 v3 = __half22float2(H2[(size_t)(p3 & 0xFFFFF) * 32]);
            float2 v4 = __half22float2(H2[(size_t)(p4 & 0xFFFFF) * 32]);
            float2 v5 = __half22float2(H2[(size_t)(p5 & 0xFFFFF) * 32]);
            float2 v6 = __half22float2(H2[(size_t)(p6 & 0xFFFFF) * 32]);
            float2 v7 = __half22float2(H2[(size_t)(p7 & 0xFFFFF) * 32]);
            int r0 = p0 >> 20, r1 = p1 >> 20, r2 = p2 >> 20, r3 = p3 >> 20;
            int r4 = p4 >> 20, r5 = p5 >> 20, r6 = p6 >> 20, r7 = p7 >> 20;
            float w0 = r0 == 0 ? n0 : (r0 == 1 ? n1 : n2);
            float w1 = r1 == 0 ? n0 : (r1 == 1 ? n1 : n2);
            float w2 = r2 == 0 ? n0 : (r2 == 1 ? n1 : n2);
            float w3 = r3 == 0 ? n0 : (r3 == 1 ? n1 : n2);
            float w4 = r4 == 0 ? n0 : (r4 == 1 ? n1 : n2);
            float w5 = r5 == 0 ? n0 : (r5 == 1 ? n1 : n2);
            float w6 = r6 == 0 ? n0 : (r6 == 1 ? n1 : n2);
            float w7 = r7 == 0 ? n0 : (r7 == 1 ? n1 : n2);
            sx += w0 * v0.x + w1 * v1.x + w2 * v2.x + w3 * v3.x
                + w4 * v4.x + w5 * v5.x + w6 * v6.x + w7 * v7.x;
            sy += w0 * v0.y + w1 * v1.y + w2 * v2.y + w3 * v3.y
                + w4 * v4.y + w5 * v5.y + w6 * v6.y + w7 * v7.y;
        }
        for (; j < m; j++) {
            int p = __shfl_sync(0xffffffffu, myid, j);
            float2 v = __half22float2(H2[(size_t)(p & 0xFFFFF) * 32]);
            int r = p >> 20;
            float w = r == 0 ? n0 : (r == 1 ? n1 : n2);
            sx += w * v.x; sy += w * v.y;
        }
    }

    int c = lane * 2;
    float ax = sx + bias[c]     + bias[64 + c]     + bias[128 + c];
    float ay = sy + bias[c + 1] + bias[64 + c + 1] + bias[128 + c + 1];
    if (HALF_OUT) {
        ax = fmaxf(ax, 0.f); ay = fmaxf(ay, 0.f);
        ((__half2*)outp)[(size_t)n * 32 + lane] = __floats2half2_rn(ax, ay);
    } else {
        *(float2*)((float*)outp + (size_t)n * 64 + c) = make_float2(ax, ay);
    }
}

// ---------------- launch ----------------
extern "C" void kernel_launch(void* const* d_in, const int* in_sizes, int n_in,
                              void* d_out, int out_size) {
    const float* x   = (const float*)d_in[0];
    const float* W1  = (const float*)d_in[1];
    const float* b1  = (const float*)d_in[2];
    const float* W2  = (const float*)d_in[3];
    const float* b2  = (const float*)d_in[4];
    const int*   src = (const int*)d_in[5];
    const int*   dst = (const int*)d_in[6];
    float* out = (float*)d_out;

    const int N = in_sizes[0] / FIN1;   // 50000

    __half *Hp, *xh, *w1h, *w2h, *h1h;
    cudaGetSymbolAddress((void**)&Hp,  g_H);
    cudaGetSymbolAddress((void**)&xh,  g_xh);
    cudaGetSymbolAddress((void**)&w1h, g_w1h);
    cudaGetSymbolAddress((void**)&w2h, g_w2h);
    cudaGetSymbolAddress((void**)&h1h, g_h1h);

    const int scanB = (N + 1023) / 1024;              // 49

    init_kernel<<<(NREL * NNODES + 255) / 256, 256>>>();
    degconv_kernel<<<DEG_B + CONVX_B + CONVW_B, 256>>>(x, W1, W2, src, dst);
    scan1_kernel<<<scanB, 256>>>(N);
    scan23_kernel<<<(N + 255) / 256, 256>>>(N, NREL * NEDGE, scanB);
    fill_kernel<<<DEG_B, 256>>>(src, dst);

    dim3 gemm_grid(NPAD / 32, NREL);
    int gather_blocks = (N * 32 + 255) / 256;

    gemm_tc<FIN1><<<gemm_grid, 256>>>(xh, w1h, Hp, N);
    gather_kernel<true><<<gather_blocks, 256>>>(Hp, b1, h1h, N);

    gemm_tc<FHID><<<gemm_grid, 256>>>(h1h, w2h, Hp, N);
    gather_kernel<false><<<gather_blocks, 256>>>(Hp, b2, out, N);
}

// round 11
// speedup vs baseline: 1.4240x; 1.4240x over previous
#include <cuda_runtime.h>
#include <cuda_fp16.h>
#include <mma.h>
#include <cstdint>
using namespace nvcuda;

#define NNODES 50000
#define NPAD   50048
#define NREL   3
#define NEDGE  600000
#define E4     (NEDGE / 4)          // 150000
#define FIN1   128
#define FHID   64
#define CSR_GRID 592                // 4 blocks/SM * 148 SMs -> co-resident

// ---------------- scratch (no allocs allowed) ----------------
__device__ __align__(128) __half g_xh[(size_t)NPAD * FIN1];
__device__ __align__(128) __half g_w1h[NREL * FIN1 * FHID];
__device__ __align__(128) __half g_w2h[NREL * FHID * FHID];
__device__ __align__(128) __half g_H[(size_t)NREL * NPAD * FHID];
__device__ __align__(128) __half g_h1h[(size_t)NPAD * FHID];   // pad rows stay .bss-zero forever
__device__ int g_odeg[NREL * NNODES];   // zeroed by cleanup at end of each graph replay
__device__ int g_ideg[NREL * NNODES];   // (first call: .bss zero)
__device__ int g_off[NNODES + 1];
__device__ int g_cursor[NNODES];
__device__ int g_eidx[NREL * NEDGE];    // packed: (r<<20) | (r*NPAD + src)
__device__ int g_bsum[64];
__device__ int g_bar;                   // software grid barrier counter (cleanup zeroes)

// ---------------- fused: degree histograms (int4) + fp16 converts ----------
#define DEG_B   ((NREL * E4 + 255) / 256)                    // 1758
#define CONVX_B ((NPAD * (FIN1 / 8) + 255) / 256)            // 3128
#define CONVW_B ((NREL * (FIN1 + FHID) * FHID + 255) / 256)  // 144

__global__ void degconv_kernel(const float* __restrict__ x,
                               const float* __restrict__ W1, const float* __restrict__ W2,
                               const int* __restrict__ src, const int* __restrict__ dst) {
    int b = blockIdx.x;
    if (b < DEG_B) {
        int t = b * 256 + threadIdx.x;
        if (t >= NREL * E4) return;
        int r = t / E4;
        int i = t - r * E4;
        int4 s4 = ((const int4*)(src + (size_t)r * NEDGE))[i];
        int4 d4 = ((const int4*)(dst + (size_t)r * NEDGE))[i];
        int rb = r * NNODES;
        atomicAdd(&g_odeg[rb + s4.x], 1);
        atomicAdd(&g_odeg[rb + s4.y], 1);
        atomicAdd(&g_odeg[rb + s4.z], 1);
        atomicAdd(&g_odeg[rb + s4.w], 1);
        atomicAdd(&g_ideg[rb + d4.x], 1);
        atomicAdd(&g_ideg[rb + d4.y], 1);
        atomicAdd(&g_ideg[rb + d4.z], 1);
        atomicAdd(&g_ideg[rb + d4.w], 1);
    } else if (b < DEG_B + CONVX_B) {
        int i = (b - DEG_B) * 256 + threadIdx.x;
        if (i >= NPAD * (FIN1 / 8)) return;
        size_t gi = (size_t)i * 8;
        int row = (int)(gi >> 7);
        union { uint4 u; __half2 h[4]; } p;
        if (row < NNODES) {
            float4 a = *(const float4*)(x + gi);
            float4 c = *(const float4*)(x + gi + 4);
            p.h[0] = __floats2half2_rn(a.x, a.y);
            p.h[1] = __floats2half2_rn(a.z, a.w);
            p.h[2] = __floats2half2_rn(c.x, c.y);
            p.h[3] = __floats2half2_rn(c.z, c.w);
        } else {
            p.h[0] = p.h[1] = p.h[2] = p.h[3] = __floats2half2_rn(0.f, 0.f);
        }
        *(uint4*)(g_xh + gi) = p.u;
    } else {
        int i = (b - DEG_B - CONVX_B) * 256 + threadIdx.x;
        const int T1 = NREL * FIN1 * FHID;
        const int T2 = NREL * FHID * FHID;
        if (i < T1) g_w1h[i] = __float2half_rn(W1[i]);
        else if (i < T1 + T2) g_w2h[i - T1] = __float2half_rn(W2[i - T1]);
    }
}

// ---------------- single-launch CSR build: scan + apply + fill --------------
// 592 co-resident blocks, software grid barrier (g_bar starts 0 every launch).
__device__ __forceinline__ void grid_barrier(int target) {
    __syncthreads();
    if (threadIdx.x == 0) {
        __threadfence();
        atomicAdd(&g_bar, 1);
        while (*(volatile int*)&g_bar < target) { }
    }
    __syncthreads();
}

__global__ void __launch_bounds__(256, 4)
csr_kernel(const int* __restrict__ src, const int* __restrict__ dst, int N) {
    const int t = threadIdx.x, bid = blockIdx.x;
    const int scanB = (N + 1023) / 1024;    // 49

    // phase 1: blocks 0..scanB-1 scan their 1024-node chunk of merged in-degree
    if (bid < scanB) {
        __shared__ int sh[256];
        int base = bid * 1024 + t * 4;
        int v[4];
        #pragma unroll
        for (int j = 0; j < 4; j++) {
            int n = base + j;
            v[j] = (n < N) ? (g_ideg[n] + g_ideg[N + n] + g_ideg[2 * N + n]) : 0;
        }
        int t0 = v[0], t1 = t0 + v[1], t2 = t1 + v[2], t3 = t2 + v[3];
        sh[t] = t3;
        __syncthreads();
        for (int off = 1; off < 256; off <<= 1) {
            int x = (t >= off) ? sh[t - off] : 0;
            __syncthreads();
            sh[t] += x;
            __syncthreads();
        }
        int excl = (t > 0) ? sh[t - 1] : 0;
        if (base + 0 < N) g_off[base + 0] = excl;
        if (base + 1 < N) g_off[base + 1] = excl + t0;
        if (base + 2 < N) g_off[base + 2] = excl + t1;
        if (base + 3 < N) g_off[base + 3] = excl + t2;
        if (t == 255) g_bsum[bid] = sh[255];
    }
    grid_barrier(CSR_GRID);

    // phase 2: every block computes prefix of the 49 block sums locally, applies
    __shared__ int pb[64];
    if (t == 0) {
        int s = 0;
        for (int i = 0; i < scanB; i++) { int v = g_bsum[i]; pb[i] = s; s += v; }
    }
    __syncthreads();
    for (int i = bid * 256 + t; i < N; i += CSR_GRID * 256) {
        int v = g_off[i] + pb[i >> 10];
        g_off[i] = v;
        g_cursor[i] = v;
    }
    if (bid == 0 && t == 0) g_off[N] = NREL * NEDGE;
    grid_barrier(2 * CSR_GRID);

    // phase 3: fill merged CSR (int4, packed relation tag)
    for (int g = bid * 256 + t; g < NREL * E4; g += CSR_GRID * 256) {
        int r = g / E4;
        int i = g - r * E4;
        int4 s4 = ((const int4*)(src + (size_t)r * NEDGE))[i];
        int4 d4 = ((const int4*)(dst + (size_t)r * NEDGE))[i];
        int tag = (r << 20) + r * NPAD;
        int p0 = atomicAdd(&g_cursor[d4.x], 1);
        int p1 = atomicAdd(&g_cursor[d4.y], 1);
        int p2 = atomicAdd(&g_cursor[d4.z], 1);
        int p3 = atomicAdd(&g_cursor[d4.w], 1);
        g_eidx[p0] = tag + s4.x;
        g_eidx[p1] = tag + s4.y;
        g_eidx[p2] = tag + s4.z;
        g_eidx[p3] = tag + s4.w;
    }
}

// ---------------- smem-staged tensor-core GEMM ------------------------------
// block tile M=64, N=64, full-K staged; 8 warps: 4 m-tiles x 2 n-halves.
template <int K>
__global__ void __launch_bounds__(256)
gemm_tc(const __half* __restrict__ Xh, const __half* __restrict__ Wh,
        __half* __restrict__ Hout, int N) {
    constexpr int AS = K + 8;                         // A smem stride (halves)
    constexpr int SBYTES = 64 * AS * 2 + K * 72 * 2;  // >= 64*72*4 for epilogue
    __shared__ __align__(16) unsigned char sbuf[SBYTES];
    __half* sA = (__half*)sbuf;
    __half* sB = (__half*)(sbuf + (size_t)64 * AS * 2);
    float*  sC = (float*)sbuf;

    const int r    = blockIdx.y;
    const int row0 = blockIdx.x * 64;
    const int tid  = threadIdx.x;
    const int wid  = tid >> 5;
    const int mt   = wid >> 1;          // 0..3: 16-row tile
    const int nh   = (wid & 1) * 32;    // 0 or 32: 32-col half

    // stage A [64 x K] (coalesced uint4)
    #pragma unroll
    for (int i = tid; i < 64 * (K / 8); i += 256) {
        int row = i / (K / 8), c8 = i % (K / 8);
        uint4 v = *(const uint4*)(Xh + (size_t)(row0 + row) * K + c8 * 8);
        *(uint4*)(sA + row * AS + c8 * 8) = v;
    }
    // stage B [K x 64]
    #pragma unroll
    for (int i = tid; i < K * 8; i += 256) {
        int row = i >> 3, c8 = i & 7;
        uint4 v = *(const uint4*)(Wh + (size_t)r * K * 64 + row * 64 + c8 * 8);
        *(uint4*)(sB + row * 72 + c8 * 8) = v;
    }
    __syncthreads();

    wmma::fragment<wmma::accumulator, 16, 16, 16, float> c0, c1;
    wmma::fill_fragment(c0, 0.0f);
    wmma::fill_fragment(c1, 0.0f);
    #pragma unroll
    for (int k0 = 0; k0 < K; k0 += 16) {
        wmma::fragment<wmma::matrix_a, 16, 16, 16, __half, wmma::row_major> a;
        wmma::fragment<wmma::matrix_b, 16, 16, 16, __half, wmma::row_major> b0, b1;
        wmma::load_matrix_sync(a, sA + mt * 16 * AS + k0, AS);
        wmma::load_matrix_sync(b0, sB + k0 * 72 + nh, 72);
        wmma::load_matrix_sync(b1, sB + k0 * 72 + nh + 16, 72);
        wmma::mma_sync(c0, a, b0, c0);
        wmma::mma_sync(c1, a, b1, c1);
    }
    __syncthreads();   // done with sA/sB; reuse as sC
    wmma::store_matrix_sync(sC + mt * 16 * 72 + nh, c0, 72, wmma::mem_row_major);
    wmma::store_matrix_sync(sC + mt * 16 * 72 + nh + 16, c1, 72, wmma::mem_row_major);
    __syncthreads();

    #pragma unroll
    for (int i = tid; i < 64 * 32; i += 256) {
        int row = i >> 5, c2 = i & 31;
        int grow = row0 + row;
        if (grow < N) {
            int od = g_odeg[r * N + grow];
            float s = rsqrtf((float)(od < 1 ? 1 : od));
            float v0 = sC[row * 72 + c2 * 2];
            float v1 = sC[row * 72 + c2 * 2 + 1];
            ((__half2*)Hout)[((size_t)r * NPAD + grow) * 32 + c2] =
                __floats2half2_rn(v0 * s, v1 * s);
        }
    }
}

// ---------------- gather over merged CSR, fused norm+bias+relu --------------
template <bool HALF_OUT>
__global__ void gather_kernel(const __half* __restrict__ H, const float* __restrict__ bias,
                              void* __restrict__ outp, int N) {
    int warp = (blockIdx.x * blockDim.x + threadIdx.x) >> 5;
    int lane = threadIdx.x & 31;
    if (warp >= N) return;
    const int n = warp;

    int d0 = g_ideg[n], d1 = g_ideg[N + n], d2 = g_ideg[2 * N + n];
    float n0 = rsqrtf((float)(d0 < 1 ? 1 : d0));
    float n1 = rsqrtf((float)(d1 < 1 ? 1 : d1));
    float n2 = rsqrtf((float)(d2 < 1 ? 1 : d2));

    const __half2* H2 = (const __half2*)H + lane;
    int beg = g_off[n];
    int end = g_off[n + 1];

    float sx = 0.f, sy = 0.f;
    for (int base = beg; base < end; base += 32) {
        int m = end - base; if (m > 32) m = 32;
        int myid = (lane < m) ? g_eidx[base + lane] : 0;
        int j = 0;
        for (; j + 8 <= m; j += 8) {
            int p0 = __shfl_sync(0xffffffffu, myid, j);
            int p1 = __shfl_sync(0xffffffffu, myid, j + 1);
            int p2 = __shfl_sync(0xffffffffu, myid, j + 2);
            int p3 = __shfl_sync(0xffffffffu, myid, j + 3);
            int p4 = __shfl_sync(0xffffffffu, myid, j + 4);
            int p5 = __shfl_sync(0xffffffffu, myid, j + 5);
            int p6 = __shfl_sync(0xffffffffu, myid, j + 6);
            int p7 = __shfl_sync(0xffffffffu, myid, j + 7);
            float2 v0 = __half22float2(H2[(size_t)(p0 & 0xFFFFF) * 32]);
            float2 v1 = __half22float2(H2[(size_t)(p1 & 0xFFFFF) * 32]);
            float2 v2 = __half22float2(H2[(size_t)(p2 & 0xFFFFF) * 32]);
            float2 v3 = __half22float2(H2[(size_t)(p3 & 0xFFFFF) * 32]);
            float2 v4 = __half22float2(H2[(size_t)(p4 & 0xFFFFF) * 32]);
            float2 v5 = __half22float2(H2[(size_t)(p5 & 0xFFFFF) * 32]);
            float2 v6 = __half22float2(H2[(size_t)(p6 & 0xFFFFF) * 32]);
            float2 v7 = __half22float2(H2[(size_t)(p7 & 0xFFFFF) * 32]);
            int r0 = p0 >> 20, r1 = p1 >> 20, r2 = p2 >> 20, r3 = p3 >> 20;
            int r4 = p4 >> 20, r5 = p5 >> 20, r6 = p6 >> 20, r7 = p7 >> 20;
            float w0 = r0 == 0 ? n0 : (r0 == 1 ? n1 : n2);
            float w1 = r1 == 0 ? n0 : (r1 == 1 ? n1 : n2);
            float w2 = r2 == 0 ? n0 : (r2 == 1 ? n1 : n2);
            float w3 = r3 == 0 ? n0 : (r3 == 1 ? n1 : n2);
            float w4 = r4 == 0 ? n0 : (r4 == 1 ? n1 : n2);
            float w5 = r5 == 0 ? n0 : (r5 == 1 ? n1 : n2);
            float w6 = r6 == 0 ? n0 : (r6 == 1 ? n1 : n2);
            float w7 = r7 == 0 ? n0 : (r7 == 1 ? n1 : n2);
            sx += w0 * v0.x + w1 * v1.x + w2 * v2.x + w3 * v3.x
                + w4 * v4.x + w5 * v5.x + w6 * v6.x + w7 * v7.x;
            sy += w0 * v0.y + w1 * v1.y + w2 * v2.y + w3 * v3.y
                + w4 * v4.y + w5 * v5.y + w6 * v6.y + w7 * v7.y;
        }
        for (; j < m; j++) {
            int p = __shfl_sync(0xffffffffu, myid, j);
            float2 v = __half22float2(H2[(size_t)(p & 0xFFFFF) * 32]);
            int rr = p >> 20;
            float w = rr == 0 ? n0 : (rr == 1 ? n1 : n2);
            sx += w * v.x; sy += w * v.y;
        }
    }

    int c = lane * 2;
    float ax = sx + bias[c]     + bias[64 + c]     + bias[128 + c];
    float ay = sy + bias[c + 1] + bias[64 + c + 1] + bias[128 + c + 1];
    if (HALF_OUT) {
        ax = fmaxf(ax, 0.f); ay = fmaxf(ay, 0.f);
        ((__half2*)outp)[(size_t)n * 32 + lane] = __floats2half2_rn(ax, ay);
    } else {
        *(float2*)((float*)outp + (size_t)n * 64 + c) = make_float2(ax, ay);
    }
}

// ---------------- cleanup: restore zeroed state for next replay -------------
__global__ void cleanup_kernel() {
    int i = blockIdx.x * blockDim.x + threadIdx.x;
    if (i < NREL * NNODES) { g_odeg[i] = 0; g_ideg[i] = 0; }
    if (i == 0) g_bar = 0;
}

// ---------------- launch ----------------
extern "C" void kernel_launch(void* const* d_in, const int* in_sizes, int n_in,
                              void* d_out, int out_size) {
    const float* x   = (const float*)d_in[0];
    const float* W1  = (const float*)d_in[1];
    const float* b1  = (const float*)d_in[2];
    const float* W2  = (const float*)d_in[3];
    const float* b2  = (const float*)d_in[4];
    const int*   src = (const int*)d_in[5];
    const int*   dst = (const int*)d_in[6];
    float* out = (float*)d_out;

    const int N = in_sizes[0] / FIN1;   // 50000

    __half *Hp, *xh, *w1h, *w2h, *h1h;
    cudaGetSymbolAddress((void**)&Hp,  g_H);
    cudaGetSymbolAddress((void**)&xh,  g_xh);
    cudaGetSymbolAddress((void**)&w1h, g_w1h);
    cudaGetSymbolAddress((void**)&w2h, g_w2h);
    cudaGetSymbolAddress((void**)&h1h, g_h1h);

    dim3 gemm_grid(NPAD / 64, NREL);
    int gather_blocks = (N * 32 + 255) / 256;

    // 0: degrees + fp16 converts (counters arrive zeroed: .bss on first call,
    //    cleanup_kernel at graph end on every subsequent replay)
    degconv_kernel<<<DEG_B + CONVX_B + CONVW_B, 256>>>(x, W1, W2, src, dst);
    // 1: full CSR build in one launch (software grid barrier)
    csr_kernel<<<CSR_GRID, 256>>>(src, dst, N);
    // 2: layer-1 GEMM
    gemm_tc<FIN1><<<gemm_grid, 256>>>(xh, w1h, Hp, N);
    // 3: layer-1 gather  (ncu captures launch #3)
    gather_kernel<true><<<gather_blocks, 256>>>(Hp, b1, h1h, N);
    // 4: layer-2 GEMM
    gemm_tc<FHID><<<gemm_grid, 256>>>(h1h, w2h, Hp, N);
    // 5: layer-2 gather
    gather_kernel<false><<<gather_blocks, 256>>>(Hp, b2, out, N);
    // 6: restore zeroed state for next replay
    cleanup_kernel<<<(NREL * NNODES + 255) / 256, 256>>>();
}

// round 12
// speedup vs baseline: 1.5745x; 1.1057x over previous
#include <cuda_runtime.h>
#include <cuda_fp16.h>
#include <mma.h>
#include <cstdint>
using namespace nvcuda;

#define NNODES 50000
#define NPAD   50048
#define NREL   3
#define NEDGE  600000
#define E4     (NEDGE / 4)          // 150000
#define FIN1   128
#define FHID   64
#define CSR_GRID 592                // 4 blocks/SM * 148 SMs -> co-resident

// ---------------- scratch (no allocs allowed) ----------------
__device__ __align__(128) __half g_xh[(size_t)NPAD * FIN1];
__device__ __align__(128) __half g_w1h[NREL * FIN1 * FHID];
__device__ __align__(128) __half g_w2h[NREL * FHID * FHID];
__device__ __align__(128) __half g_H[(size_t)NREL * NPAD * FHID];
__device__ __align__(128) __half g_h1h[(size_t)NPAD * FHID];   // pad rows stay .bss-zero
__device__ __align__(128) float  g_cb1[FHID];                  // combined bias layer1
__device__ __align__(128) float  g_cb2[FHID];
__device__ int   g_odeg[NREL * NNODES];   // zeroed by cleanup at graph end
__device__ int   g_ideg[NREL * NNODES];
__device__ float g_inorm[NREL * NNODES];  // rsqrt(max(ideg,1))
__device__ int   g_off[NNODES + 1];
__device__ int   g_cursor[NNODES];
__device__ int   g_eidx[NREL * NEDGE];    // r*NPAD + src  (H row index)
__device__ float g_ewt[NREL * NEDGE];     // per-edge dst-side norm
__device__ int   g_bsum[64];
__device__ int   g_bar;

// ---------------- fused: degree histograms (int4) + fp16 converts ----------
#define DEG_B   ((NREL * E4 + 255) / 256)                    // 1758
#define CONVX_B ((NPAD * (FIN1 / 8) + 255) / 256)            // 3128
#define CONVW_B ((NREL * (FIN1 + FHID) * FHID + 255) / 256)  // 144

__global__ void degconv_kernel(const float* __restrict__ x,
                               const float* __restrict__ W1, const float* __restrict__ W2,
                               const float* __restrict__ b1, const float* __restrict__ b2,
                               const int* __restrict__ src, const int* __restrict__ dst) {
    int b = blockIdx.x;
    if (b < DEG_B) {
        int t = b * 256 + threadIdx.x;
        if (t >= NREL * E4) return;
        int r = t / E4;
        int i = t - r * E4;
        int4 s4 = ((const int4*)(src + (size_t)r * NEDGE))[i];
        int4 d4 = ((const int4*)(dst + (size_t)r * NEDGE))[i];
        int rb = r * NNODES;
        atomicAdd(&g_odeg[rb + s4.x], 1);
        atomicAdd(&g_odeg[rb + s4.y], 1);
        atomicAdd(&g_odeg[rb + s4.z], 1);
        atomicAdd(&g_odeg[rb + s4.w], 1);
        atomicAdd(&g_ideg[rb + d4.x], 1);
        atomicAdd(&g_ideg[rb + d4.y], 1);
        atomicAdd(&g_ideg[rb + d4.z], 1);
        atomicAdd(&g_ideg[rb + d4.w], 1);
    } else if (b < DEG_B + CONVX_B) {
        int i = (b - DEG_B) * 256 + threadIdx.x;
        if (i >= NPAD * (FIN1 / 8)) return;
        size_t gi = (size_t)i * 8;
        int row = (int)(gi >> 7);
        union { uint4 u; __half2 h[4]; } p;
        if (row < NNODES) {
            float4 a = *(const float4*)(x + gi);
            float4 c = *(const float4*)(x + gi + 4);
            p.h[0] = __floats2half2_rn(a.x, a.y);
            p.h[1] = __floats2half2_rn(a.z, a.w);
            p.h[2] = __floats2half2_rn(c.x, c.y);
            p.h[3] = __floats2half2_rn(c.z, c.w);
        } else {
            p.h[0] = p.h[1] = p.h[2] = p.h[3] = __floats2half2_rn(0.f, 0.f);
        }
        *(uint4*)(g_xh + gi) = p.u;
    } else {
        int i = (b - DEG_B - CONVX_B) * 256 + threadIdx.x;
        const int T1 = NREL * FIN1 * FHID;
        const int T2 = NREL * FHID * FHID;
        if (i < T1) g_w1h[i] = __float2half_rn(W1[i]);
        else if (i < T1 + T2) g_w2h[i - T1] = __float2half_rn(W2[i - T1]);
        if (b == DEG_B + CONVX_B && threadIdx.x < FHID) {
            int c = threadIdx.x;
            g_cb1[c] = b1[c] + b1[FHID + c] + b1[2 * FHID + c];
            g_cb2[c] = b2[c] + b2[FHID + c] + b2[2 * FHID + c];
        }
    }
}

// ---------------- single-launch CSR build: scan + apply + fill --------------
__device__ __forceinline__ void grid_barrier(int target) {
    __syncthreads();
    if (threadIdx.x == 0) {
        __threadfence();
        atomicAdd(&g_bar, 1);
        while (*(volatile int*)&g_bar < target) { }
        __threadfence();
    }
    __syncthreads();
}

__global__ void __launch_bounds__(256, 4)
csr_kernel(const int* __restrict__ src, const int* __restrict__ dst, int N) {
    const int t = threadIdx.x, bid = blockIdx.x;
    const int scanB = (N + 1023) / 1024;    // 49

    // phase 1: blocks 0..scanB-1 scan their 1024-node chunk of merged in-degree
    if (bid < scanB) {
        __shared__ int sh[256];
        int base = bid * 1024 + t * 4;
        int v[4];
        #pragma unroll
        for (int j = 0; j < 4; j++) {
            int n = base + j;
            v[j] = (n < N) ? (g_ideg[n] + g_ideg[N + n] + g_ideg[2 * N + n]) : 0;
        }
        int t0 = v[0], t1 = t0 + v[1], t2 = t1 + v[2], t3 = t2 + v[3];
        sh[t] = t3;
        __syncthreads();
        for (int off = 1; off < 256; off <<= 1) {
            int x = (t >= off) ? sh[t - off] : 0;
            __syncthreads();
            sh[t] += x;
            __syncthreads();
        }
        int excl = (t > 0) ? sh[t - 1] : 0;
        if (base + 0 < N) g_off[base + 0] = excl;
        if (base + 1 < N) g_off[base + 1] = excl + t0;
        if (base + 2 < N) g_off[base + 2] = excl + t1;
        if (base + 3 < N) g_off[base + 3] = excl + t2;
        if (t == 255) g_bsum[bid] = sh[255];
    }
    grid_barrier(CSR_GRID);

    // phase 2: apply block-sum prefix; also precompute in-degree norms (3N)
    __shared__ int pb[64];
    if (t == 0) {
        int s = 0;
        for (int i = 0; i < scanB; i++) { int v = g_bsum[i]; pb[i] = s; s += v; }
    }
    __syncthreads();
    for (int i = bid * 256 + t; i < N; i += CSR_GRID * 256) {
        int v = g_off[i] + pb[i >> 10];
        g_off[i] = v;
        g_cursor[i] = v;
    }
    for (int i = bid * 256 + t; i < NREL * N; i += CSR_GRID * 256) {
        int id = g_ideg[i];
        g_inorm[i] = rsqrtf((float)(id < 1 ? 1 : id));
    }
    if (bid == 0 && t == 0) g_off[N] = NREL * NEDGE;
    grid_barrier(2 * CSR_GRID);

    // phase 3: fill merged CSR: H-row index + per-edge dst norm weight
    for (int g = bid * 256 + t; g < NREL * E4; g += CSR_GRID * 256) {
        int r = g / E4;
        int i = g - r * E4;
        int4 s4 = ((const int4*)(src + (size_t)r * NEDGE))[i];
        int4 d4 = ((const int4*)(dst + (size_t)r * NEDGE))[i];
        int rn = r * NNODES, rp = r * NPAD;
        float w0 = g_inorm[rn + d4.x];
        float w1 = g_inorm[rn + d4.y];
        float w2 = g_inorm[rn + d4.z];
        float w3 = g_inorm[rn + d4.w];
        int p0 = atomicAdd(&g_cursor[d4.x], 1);
        int p1 = atomicAdd(&g_cursor[d4.y], 1);
        int p2 = atomicAdd(&g_cursor[d4.z], 1);
        int p3 = atomicAdd(&g_cursor[d4.w], 1);
        g_eidx[p0] = rp + s4.x;  g_ewt[p0] = w0;
        g_eidx[p1] = rp + s4.y;  g_ewt[p1] = w1;
        g_eidx[p2] = rp + s4.z;  g_ewt[p2] = w2;
        g_eidx[p3] = rp + s4.w;  g_ewt[p3] = w3;
    }
}

// ---------------- smem-staged tensor-core GEMM ------------------------------
template <int K>
__global__ void __launch_bounds__(256)
gemm_tc(const __half* __restrict__ Xh, const __half* __restrict__ Wh,
        __half* __restrict__ Hout, int N) {
    constexpr int AS = K + 8;
    constexpr int SBYTES = 64 * AS * 2 + K * 72 * 2;
    __shared__ __align__(16) unsigned char sbuf[SBYTES];
    __half* sA = (__half*)sbuf;
    __half* sB = (__half*)(sbuf + (size_t)64 * AS * 2);
    float*  sC = (float*)sbuf;

    const int r    = blockIdx.y;
    const int row0 = blockIdx.x * 64;
    const int tid  = threadIdx.x;
    const int wid  = tid >> 5;
    const int mt   = wid >> 1;
    const int nh   = (wid & 1) * 32;

    #pragma unroll
    for (int i = tid; i < 64 * (K / 8); i += 256) {
        int row = i / (K / 8), c8 = i % (K / 8);
        uint4 v = *(const uint4*)(Xh + (size_t)(row0 + row) * K + c8 * 8);
        *(uint4*)(sA + row * AS + c8 * 8) = v;
    }
    #pragma unroll
    for (int i = tid; i < K * 8; i += 256) {
        int row = i >> 3, c8 = i & 7;
        uint4 v = *(const uint4*)(Wh + (size_t)r * K * 64 + row * 64 + c8 * 8);
        *(uint4*)(sB + row * 72 + c8 * 8) = v;
    }
    __syncthreads();

    wmma::fragment<wmma::accumulator, 16, 16, 16, float> c0, c1;
    wmma::fill_fragment(c0, 0.0f);
    wmma::fill_fragment(c1, 0.0f);
    #pragma unroll
    for (int k0 = 0; k0 < K; k0 += 16) {
        wmma::fragment<wmma::matrix_a, 16, 16, 16, __half, wmma::row_major> a;
        wmma::fragment<wmma::matrix_b, 16, 16, 16, __half, wmma::row_major> b0, b1;
        wmma::load_matrix_sync(a, sA + mt * 16 * AS + k0, AS);
        wmma::load_matrix_sync(b0, sB + k0 * 72 + nh, 72);
        wmma::load_matrix_sync(b1, sB + k0 * 72 + nh + 16, 72);
        wmma::mma_sync(c0, a, b0, c0);
        wmma::mma_sync(c1, a, b1, c1);
    }
    __syncthreads();
    wmma::store_matrix_sync(sC + mt * 16 * 72 + nh, c0, 72, wmma::mem_row_major);
    wmma::store_matrix_sync(sC + mt * 16 * 72 + nh + 16, c1, 72, wmma::mem_row_major);
    __syncthreads();

    #pragma unroll
    for (int i = tid; i < 64 * 32; i += 256) {
        int row = i >> 5, c2 = i & 31;
        int grow = row0 + row;
        if (grow < N) {
            int od = g_odeg[r * N + grow];
            float s = rsqrtf((float)(od < 1 ? 1 : od));
            float v0 = sC[row * 72 + c2 * 2];
            float v1 = sC[row * 72 + c2 * 2 + 1];
            ((__half2*)Hout)[((size_t)r * NPAD + grow) * 32 + c2] =
                __floats2half2_rn(v0 * s, v1 * s);
        }
    }
}

// ---------------- gather: 4 edges/warp-iter, precomputed weights ------------
// lanes in 4 groups of 8; lane handles 8 channels (one uint4 of halves).
template <bool HALF_OUT>
__global__ void gather_kernel(const __half* __restrict__ H, const float* __restrict__ cb,
                              void* __restrict__ outp, int N) {
    int warp = (blockIdx.x * blockDim.x + threadIdx.x) >> 5;
    int lane = threadIdx.x & 31;
    if (warp >= N) return;
    const int n = warp;
    const int g = lane >> 3, s = lane & 7;

    const uint4* Hv = (const uint4*)H;   // row = 8 uint4
    int beg = g_off[n];
    int end = g_off[n + 1];

    float acc[8] = {};
    for (int base = beg; base < end; base += 32) {
        int m = end - base; if (m > 32) m = 32;
        int   myid = 0;
        float mywt = 0.f;
        if (lane < m) { myid = g_eidx[base + lane]; mywt = g_ewt[base + lane]; }
        int jmax = (m + 3) >> 2;
        for (int j = 0; j < jmax; j++) {
            int e = j * 4 + g;                        // e <= 31 always
            int   id = __shfl_sync(0xffffffffu, myid, e);
            float wt = __shfl_sync(0xffffffffu, mywt, e);   // 0 for e >= m
            uint4 hv = Hv[(size_t)id * 8 + s];
            union { uint4 u; __half2 h[4]; } p; p.u = hv;
            float2 f0 = __half22float2(p.h[0]);
            float2 f1 = __half22float2(p.h[1]);
            float2 f2 = __half22float2(p.h[2]);
            float2 f3 = __half22float2(p.h[3]);
            acc[0] += wt * f0.x; acc[1] += wt * f0.y;
            acc[2] += wt * f1.x; acc[3] += wt * f1.y;
            acc[4] += wt * f2.x; acc[5] += wt * f2.y;
            acc[6] += wt * f3.x; acc[7] += wt * f3.y;
        }
    }

    // reduce across the 4 groups (lanes with equal s)
    #pragma unroll
    for (int off = 8; off < 32; off <<= 1) {
        #pragma unroll
        for (int k = 0; k < 8; k++)
            acc[k] += __shfl_xor_sync(0xffffffffu, acc[k], off);
    }

    if (lane < 8) {
        int c = lane * 8;
        #pragma unroll
        for (int k = 0; k < 8; k++) acc[k] += cb[c + k];
        if (HALF_OUT) {
            #pragma unroll
            for (int k = 0; k < 8; k++) acc[k] = fmaxf(acc[k], 0.f);
            union { uint4 u; __half2 h[4]; } p;
            p.h[0] = __floats2half2_rn(acc[0], acc[1]);
            p.h[1] = __floats2half2_rn(acc[2], acc[3]);
            p.h[2] = __floats2half2_rn(acc[4], acc[5]);
            p.h[3] = __floats2half2_rn(acc[6], acc[7]);
            *(uint4*)((__half*)outp + (size_t)n * 64 + c) = p.u;
        } else {
            float* o = (float*)outp + (size_t)n * 64 + c;
            *(float4*)o       = make_float4(acc[0], acc[1], acc[2], acc[3]);
            *(float4*)(o + 4) = make_float4(acc[4], acc[5], acc[6], acc[7]);
        }
    }
}

// ---------------- cleanup: restore zeroed state for next replay -------------
__global__ void cleanup_kernel() {
    int i = blockIdx.x * blockDim.x + threadIdx.x;
    if (i < NREL * NNODES) { g_odeg[i] = 0; g_ideg[i] = 0; }
    if (i == 0) g_bar = 0;
}

// ---------------- launch ----------------
extern "C" void kernel_launch(void* const* d_in, const int* in_sizes, int n_in,
                              void* d_out, int out_size) {
    const float* x   = (const float*)d_in[0];
    const float* W1  = (const float*)d_in[1];
    const float* b1  = (const float*)d_in[2];
    const float* W2  = (const float*)d_in[3];
    const float* b2  = (const float*)d_in[4];
    const int*   src = (const int*)d_in[5];
    const int*   dst = (const int*)d_in[6];
    float* out = (float*)d_out;

    const int N = in_sizes[0] / FIN1;   // 50000

    __half *Hp, *xh, *w1h, *w2h, *h1h;
    float *cb1, *cb2;
    cudaGetSymbolAddress((void**)&Hp,  g_H);
    cudaGetSymbolAddress((void**)&xh,  g_xh);
    cudaGetSymbolAddress((void**)&w1h, g_w1h);
    cudaGetSymbolAddress((void**)&w2h, g_w2h);
    cudaGetSymbolAddress((void**)&h1h, g_h1h);
    cudaGetSymbolAddress((void**)&cb1, g_cb1);
    cudaGetSymbolAddress((void**)&cb2, g_cb2);

    dim3 gemm_grid(NPAD / 64, NREL);
    int gather_blocks = (N * 32 + 255) / 256;

    degconv_kernel<<<DEG_B + CONVX_B + CONVW_B, 256>>>(x, W1, W2, b1, b2, src, dst);
    csr_kernel<<<CSR_GRID, 256>>>(src, dst, N);
    gemm_tc<FIN1><<<gemm_grid, 256>>>(xh, w1h, Hp, N);
    gather_kernel<true><<<gather_blocks, 256>>>(Hp, cb1, h1h, N);
    gemm_tc<FHID><<<gemm_grid, 256>>>(h1h, w2h, Hp, N);
    gather_kernel<false><<<gather_blocks, 256>>>(Hp, cb2, out, N);
    cleanup_kernel<<<(NREL * NNODES + 255) / 256, 256>>>();
}

// round 14
// speedup vs baseline: 1.6511x; 1.0486x over previous
#include <cuda_runtime.h>
#include <cuda_fp16.h>
#include <mma.h>
#include <cstdint>
using namespace nvcuda;

#define NNODES 50000
#define NPAD   50048
#define NREL   3
#define NEDGE  600000
#define E4     (NEDGE / 4)          // 150000
#define E8     (NEDGE / 8)          // 75000
#define FIN1   128
#define FHID   64
#define CSR_GRID 592                // 4 blocks/SM * 148 SMs -> co-resident

// ---------------- scratch (no allocs allowed) ----------------
__device__ __align__(128) __half g_xh[(size_t)NPAD * FIN1];
__device__ __align__(128) __half g_w1h[NREL * FIN1 * FHID];
__device__ __align__(128) __half g_w2h[NREL * FHID * FHID];
__device__ __align__(128) __half g_H[(size_t)NREL * NPAD * FHID];
__device__ __align__(128) __half g_h1h[(size_t)NPAD * FHID];   // pad rows stay .bss-zero
__device__ __align__(128) float  g_cb1[FHID];
__device__ __align__(128) float  g_cb2[FHID];
__device__ int   g_odeg[NREL * NNODES];   // zeroed by gather2 tail each replay
__device__ int   g_ideg[NREL * NNODES];
__device__ float g_inorm[NREL * NNODES];
__device__ int   g_off[NNODES + 1];
__device__ int   g_cursor[NNODES];
__device__ int   g_eidx[NREL * NEDGE];    // r*NPAD + src  (H row index)
__device__ float g_ewt[NREL * NEDGE];     // per-edge dst-side norm
__device__ int   g_bsum[64];
__device__ int   g_bar;

// ---------------- fused: degree histograms (2x int4) + fp16 converts --------
#define DEG_B   ((NREL * E8 + 255) / 256)                    // 879
#define CONVX_B ((NPAD * (FIN1 / 8) + 255) / 256)            // 3128
#define CONVW_B ((NREL * (FIN1 + FHID) * FHID + 255) / 256)  // 144

__global__ void degconv_kernel(const float* __restrict__ x,
                               const float* __restrict__ W1, const float* __restrict__ W2,
                               const float* __restrict__ b1, const float* __restrict__ b2,
                               const int* __restrict__ src, const int* __restrict__ dst) {
    int b = blockIdx.x;
    if (b < DEG_B) {
        int t = b * 256 + threadIdx.x;
        if (t >= NREL * E8) return;
        int r = t / E8;
        int i = (t - r * E8) * 2;
        const int4* sp = (const int4*)(src + (size_t)r * NEDGE);
        const int4* dp = (const int4*)(dst + (size_t)r * NEDGE);
        int4 sa = sp[i], sb = sp[i + 1];
        int4 da = dp[i], db = dp[i + 1];
        int rb = r * NNODES;
        atomicAdd(&g_odeg[rb + sa.x], 1); atomicAdd(&g_odeg[rb + sa.y], 1);
        atomicAdd(&g_odeg[rb + sa.z], 1); atomicAdd(&g_odeg[rb + sa.w], 1);
        atomicAdd(&g_odeg[rb + sb.x], 1); atomicAdd(&g_odeg[rb + sb.y], 1);
        atomicAdd(&g_odeg[rb + sb.z], 1); atomicAdd(&g_odeg[rb + sb.w], 1);
        atomicAdd(&g_ideg[rb + da.x], 1); atomicAdd(&g_ideg[rb + da.y], 1);
        atomicAdd(&g_ideg[rb + da.z], 1); atomicAdd(&g_ideg[rb + da.w], 1);
        atomicAdd(&g_ideg[rb + db.x], 1); atomicAdd(&g_ideg[rb + db.y], 1);
        atomicAdd(&g_ideg[rb + db.z], 1); atomicAdd(&g_ideg[rb + db.w], 1);
    } else if (b < DEG_B + CONVX_B) {
        int i = (b - DEG_B) * 256 + threadIdx.x;
        if (i >= NPAD * (FIN1 / 8)) return;
        size_t gi = (size_t)i * 8;
        int row = (int)(gi >> 7);
        union { uint4 u; __half2 h[4]; } p;
        if (row < NNODES) {
            float4 a = *(const float4*)(x + gi);
            float4 c = *(const float4*)(x + gi + 4);
            p.h[0] = __floats2half2_rn(a.x, a.y);
            p.h[1] = __floats2half2_rn(a.z, a.w);
            p.h[2] = __floats2half2_rn(c.x, c.y);
            p.h[3] = __floats2half2_rn(c.z, c.w);
        } else {
            p.h[0] = p.h[1] = p.h[2] = p.h[3] = __floats2half2_rn(0.f, 0.f);
        }
        *(uint4*)(g_xh + gi) = p.u;
    } else {
        int i = (b - DEG_B - CONVX_B) * 256 + threadIdx.x;
        const int T1 = NREL * FIN1 * FHID;
        const int T2 = NREL * FHID * FHID;
        if (i < T1) g_w1h[i] = __float2half_rn(W1[i]);
        else if (i < T1 + T2) g_w2h[i - T1] = __float2half_rn(W2[i - T1]);
        if (b == DEG_B + CONVX_B && threadIdx.x < FHID) {
            int c = threadIdx.x;
            g_cb1[c] = b1[c] + b1[FHID + c] + b1[2 * FHID + c];
            g_cb2[c] = b2[c] + b2[FHID + c] + b2[2 * FHID + c];
        }
    }
}

// ---------------- single-launch CSR build: scan + apply + fill --------------
__device__ __forceinline__ void grid_barrier(int target) {
    __syncthreads();
    if (threadIdx.x == 0) {
        __threadfence();
        atomicAdd(&g_bar, 1);
        while (*(volatile int*)&g_bar < target) { }
        __threadfence();
    }
    __syncthreads();
}

__global__ void __launch_bounds__(256, 4)
csr_kernel(const int* __restrict__ src, const int* __restrict__ dst, int N) {
    const int t = threadIdx.x, bid = blockIdx.x;
    const int scanB = (N + 1023) / 1024;    // 49

    if (bid < scanB) {
        __shared__ int sh[256];
        int base = bid * 1024 + t * 4;
        int v[4];
        #pragma unroll
        for (int j = 0; j < 4; j++) {
            int n = base + j;
            v[j] = (n < N) ? (g_ideg[n] + g_ideg[N + n] + g_ideg[2 * N + n]) : 0;
        }
        int t0 = v[0], t1 = t0 + v[1], t2 = t1 + v[2], t3 = t2 + v[3];
        sh[t] = t3;
        __syncthreads();
        for (int off = 1; off < 256; off <<= 1) {
            int x = (t >= off) ? sh[t - off] : 0;
            __syncthreads();
            sh[t] += x;
            __syncthreads();
        }
        int excl = (t > 0) ? sh[t - 1] : 0;
        if (base + 0 < N) g_off[base + 0] = excl;
        if (base + 1 < N) g_off[base + 1] = excl + t0;
        if (base + 2 < N) g_off[base + 2] = excl + t1;
        if (base + 3 < N) g_off[base + 3] = excl + t2;
        if (t == 255) g_bsum[bid] = sh[255];
    }
    grid_barrier(CSR_GRID);

    __shared__ int pb[64];
    if (t == 0) {
        int s = 0;
        for (int i = 0; i < scanB; i++) { int v = g_bsum[i]; pb[i] = s; s += v; }
    }
    __syncthreads();
    for (int i = bid * 256 + t; i < N; i += CSR_GRID * 256) {
        int v = g_off[i] + pb[i >> 10];
        g_off[i] = v;
        g_cursor[i] = v;
    }
    for (int i = bid * 256 + t; i < NREL * N; i += CSR_GRID * 256) {
        int id = g_ideg[i];
        g_inorm[i] = rsqrtf((float)(id < 1 ? 1 : id));
    }
    if (bid == 0 && t == 0) g_off[N] = NREL * NEDGE;
    grid_barrier(2 * CSR_GRID);

    for (int g = bid * 256 + t; g < NREL * E4; g += CSR_GRID * 256) {
        int r = g / E4;
        int i = g - r * E4;
        int4 s4 = ((const int4*)(src + (size_t)r * NEDGE))[i];
        int4 d4 = ((const int4*)(dst + (size_t)r * NEDGE))[i];
        int rn = r * NNODES, rp = r * NPAD;
        float w0 = g_inorm[rn + d4.x];
        float w1 = g_inorm[rn + d4.y];
        float w2 = g_inorm[rn + d4.z];
        float w3 = g_inorm[rn + d4.w];
        int p0 = atomicAdd(&g_cursor[d4.x], 1);
        int p1 = atomicAdd(&g_cursor[d4.y], 1);
        int p2 = atomicAdd(&g_cursor[d4.z], 1);
        int p3 = atomicAdd(&g_cursor[d4.w], 1);
        g_eidx[p0] = rp + s4.x;  g_ewt[p0] = w0;
        g_eidx[p1] = rp + s4.y;  g_ewt[p1] = w1;
        g_eidx[p2] = rp + s4.z;  g_ewt[p2] = w2;
        g_eidx[p3] = rp + s4.w;  g_ewt[p3] = w3;
    }
}

// ---------------- smem-staged tensor-core GEMM ------------------------------
template <int K>
__global__ void __launch_bounds__(256)
gemm_tc(const __half* __restrict__ Xh, const __half* __restrict__ Wh,
        __half* __restrict__ Hout, int N) {
    constexpr int AS = K + 8;
    constexpr int SBYTES = 64 * AS * 2 + K * 72 * 2;
    __shared__ __align__(16) unsigned char sbuf[SBYTES];
    __half* sA = (__half*)sbuf;
    __half* sB = (__half*)(sbuf + (size_t)64 * AS * 2);
    float*  sC = (float*)sbuf;

    const int r    = blockIdx.y;
    const int row0 = blockIdx.x * 64;
    const int tid  = threadIdx.x;
    const int wid  = tid >> 5;
    const int mt   = wid >> 1;
    const int nh   = (wid & 1) * 32;

    #pragma unroll
    for (int i = tid; i < 64 * (K / 8); i += 256) {
        int row = i / (K / 8), c8 = i % (K / 8);
        uint4 v = *(const uint4*)(Xh + (size_t)(row0 + row) * K + c8 * 8);
        *(uint4*)(sA + row * AS + c8 * 8) = v;
    }
    #pragma unroll
    for (int i = tid; i < K * 8; i += 256) {
        int row = i >> 3, c8 = i & 7;
        uint4 v = *(const uint4*)(Wh + (size_t)r * K * 64 + row * 64 + c8 * 8);
        *(uint4*)(sB + row * 72 + c8 * 8) = v;
    }
    __syncthreads();

    wmma::fragment<wmma::accumulator, 16, 16, 16, float> c0, c1;
    wmma::fill_fragment(c0, 0.0f);
    wmma::fill_fragment(c1, 0.0f);
    #pragma unroll
    for (int k0 = 0; k0 < K; k0 += 16) {
        wmma::fragment<wmma::matrix_a, 16, 16, 16, __half, wmma::row_major> a;
        wmma::fragment<wmma::matrix_b, 16, 16, 16, __half, wmma::row_major> b0, b1;
        wmma::load_matrix_sync(a, sA + mt * 16 * AS + k0, AS);
        wmma::load_matrix_sync(b0, sB + k0 * 72 + nh, 72);
        wmma::load_matrix_sync(b1, sB + k0 * 72 + nh + 16, 72);
        wmma::mma_sync(c0, a, b0, c0);
        wmma::mma_sync(c1, a, b1, c1);
    }
    __syncthreads();
    wmma::store_matrix_sync(sC + mt * 16 * 72 + nh, c0, 72, wmma::mem_row_major);
    wmma::store_matrix_sync(sC + mt * 16 * 72 + nh + 16, c1, 72, wmma::mem_row_major);
    __syncthreads();

    #pragma unroll
    for (int i = tid; i < 64 * 32; i += 256) {
        int row = i >> 5, c2 = i & 31;
        int grow = row0 + row;
        if (grow < N) {
            int od = g_odeg[r * N + grow];
            float s = rsqrtf((float)(od < 1 ? 1 : od));
            float v0 = sC[row * 72 + c2 * 2];
            float v1 = sC[row * 72 + c2 * 2 + 1];
            ((__half2*)Hout)[((size_t)r * NPAD + grow) * 32 + c2] =
                __floats2half2_rn(v0 * s, v1 * s);
        }
    }
}

// ---------------- gather: 8 edges/warp-iter (2 loads in flight per lane) ----
// lanes in 4 groups of 8; lane handles 8 channels (one uint4 of halves).
// CLEANUP=true (layer 2): tail also re-zeroes degree counters for next replay.
template <bool HALF_OUT, bool CLEANUP>
__global__ void gather_kernel(const __half* __restrict__ H, const float* __restrict__ cb,
                              void* __restrict__ outp, int N) {
    int warp = (blockIdx.x * blockDim.x + threadIdx.x) >> 5;
    int lane = threadIdx.x & 31;
    if (warp >= N) return;
    const int n = warp;
    const int g = lane >> 3, s = lane & 7;

    const uint4* Hv = (const uint4*)H;   // row = 8 uint4
    int beg = g_off[n];
    int end = g_off[n + 1];

    float acc[8] = {};
    for (int base = beg; base < end; base += 32) {
        int m = end - base; if (m > 32) m = 32;
        int   myid = 0;
        float mywt = 0.f;
        if (lane < m) { myid = g_eidx[base + lane]; mywt = g_ewt[base + lane]; }
        int jmax = (m + 7) >> 3;
        for (int j = 0; j < jmax; j++) {
            int e0 = j * 8 + g;
            int e1 = e0 + 4;
            int   id0 = __shfl_sync(0xffffffffu, myid, e0);
            float wt0 = __shfl_sync(0xffffffffu, mywt, e0);
            int   id1 = __shfl_sync(0xffffffffu, myid, e1);
            float wt1 = __shfl_sync(0xffffffffu, mywt, e1);
            uint4 hv0 = Hv[(size_t)id0 * 8 + s];
            uint4 hv1 = Hv[(size_t)id1 * 8 + s];
            union { uint4 u; __half2 h[4]; } p0, p1;
            p0.u = hv0; p1.u = hv1;
            float2 a0 = __half22float2(p0.h[0]);
            float2 a1 = __half22float2(p0.h[1]);
            float2 a2 = __half22float2(p0.h[2]);
            float2 a3 = __half22float2(p0.h[3]);
            acc[0] += wt0 * a0.x; acc[1] += wt0 * a0.y;
            acc[2] += wt0 * a1.x; acc[3] += wt0 * a1.y;
            acc[4] += wt0 * a2.x; acc[5] += wt0 * a2.y;
            acc[6] += wt0 * a3.x; acc[7] += wt0 * a3.y;
            float2 b0 = __half22float2(p1.h[0]);
            float2 b1 = __half22float2(p1.h[1]);
            float2 b2 = __half22float2(p1.h[2]);
            float2 b3 = __half22float2(p1.h[3]);
            acc[0] += wt1 * b0.x; acc[1] += wt1 * b0.y;
            acc[2] += wt1 * b1.x; acc[3] += wt1 * b1.y;
            acc[4] += wt1 * b2.x; acc[5] += wt1 * b2.y;
            acc[6] += wt1 * b3.x; acc[7] += wt1 * b3.y;
        }
    }

    #pragma unroll
    for (int off = 8; off < 32; off <<= 1) {
        #pragma unroll
        for (int k = 0; k < 8; k++)
            acc[k] += __shfl_xor_sync(0xffffffffu, acc[k], off);
    }

    if (lane < 8) {
        int c = lane * 8;
        #pragma unroll
        for (int k = 0; k < 8; k++) acc[k] += cb[c + k];
        if (HALF_OUT) {
            #pragma unroll
            for (int k = 0; k < 8; k++) acc[k] = fmaxf(acc[k], 0.f);
            union { uint4 u; __half2 h[4]; } p;
            p.h[0] = __floats2half2_rn(acc[0], acc[1]);
            p.h[1] = __floats2half2_rn(acc[2], acc[3]);
            p.h[2] = __floats2half2_rn(acc[4], acc[5]);
            p.h[3] = __floats2half2_rn(acc[6], acc[7]);
            *(uint4*)((__half*)outp + (size_t)n * 64 + c) = p.u;
        } else {
            float* o = (float*)outp + (size_t)n * 64 + c;
            *(float4*)o       = make_float4(acc[0], acc[1], acc[2], acc[3]);
            *(float4*)(o + 4) = make_float4(acc[4], acc[5], acc[6], acc[7]);
        }
    }
    if (CLEANUP) {
        // re-zero degree counters for the next graph replay
        if (lane >= 8 && lane < 11) g_odeg[(lane - 8) * N + n] = 0;
        if (lane >= 11 && lane < 14) g_ideg[(lane - 11) * N + n] = 0;
        if (n == 0 && lane == 14) g_bar = 0;
    }
}

// ---------------- launch ----------------
extern "C" void kernel_launch(void* const* d_in, const int* in_sizes, int n_in,
                              void* d_out, int out_size) {
    const float* x   = (const float*)d_in[0];
    const float* W1  = (const float*)d_in[1];
    const float* b1  = (const float*)d_in[2];
    const float* W2  = (const float*)d_in[3];
    const float* b2  = (const float*)d_in[4];
    const int*   src = (const int*)d_in[5];
    const int*   dst = (const int*)d_in[6];
    float* out = (float*)d_out;

    const int N = in_sizes[0] / FIN1;   // 50000

    __half *Hp, *xh, *w1h, *w2h, *h1h;
    float *cb1, *cb2;
    cudaGetSymbolAddress((void**)&Hp,  g_H);
    cudaGetSymbolAddress((void**)&xh,  g_xh);
    cudaGetSymbolAddress((void**)&w1h, g_w1h);
    cudaGetSymbolAddress((void**)&w2h, g_w2h);
    cudaGetSymbolAddress((void**)&h1h, g_h1h);
    cudaGetSymbolAddress((void**)&cb1, g_cb1);
    cudaGetSymbolAddress((void**)&cb2, g_cb2);

    dim3 gemm_grid(NPAD / 64, NREL);
    int gather_blocks = (N * 32 + 255) / 256;

    degconv_kernel<<<DEG_B + CONVX_B + CONVW_B, 256>>>(x, W1, W2, b1, b2, src, dst);
    csr_kernel<<<CSR_GRID, 256>>>(src, dst, N);
    gemm_tc<FIN1><<<gemm_grid, 256>>>(xh, w1h, Hp, N);
    gather_kernel<true, false><<<gather_blocks, 256>>>(Hp, cb1, h1h, N);
    gemm_tc<FHID><<<gemm_grid, 256>>>(h1h, w2h, Hp, N);
    gather_kernel<false, true><<<gather_blocks, 256>>>(Hp, cb2, out, N);
}

// round 16
// speedup vs baseline: 1.7160x; 1.0393x over previous
#include <cuda_runtime.h>
#include <cuda_fp16.h>
#include <mma.h>
#include <cstdint>
using namespace nvcuda;

#define NNODES 50000
#define NPAD   50048
#define NREL   3
#define NEDGE  600000
#define E4     (NEDGE / 4)          // 150000
#define E8     (NEDGE / 8)          // 75000
#define FIN1   128
#define FHID   64
#define CSR_GRID 592                // 4 blocks/SM * 148 SMs -> co-resident

// ---------------- scratch (no allocs allowed) ----------------
__device__ __align__(128) __half g_xh[(size_t)NPAD * FIN1];
__device__ __align__(128) __half g_w1h[NREL * FIN1 * FHID];
__device__ __align__(128) __half g_w2h[NREL * FHID * FHID];
__device__ __align__(128) __half g_H[(size_t)NREL * NPAD * FHID];
__device__ __align__(128) __half g_h1h[(size_t)NPAD * FHID];   // pad rows stay .bss-zero
__device__ __align__(128) float  g_cb1[FHID];
__device__ __align__(128) float  g_cb2[FHID];
__device__ int   g_odeg[NREL * NNODES];   // zeroed by gather2 tail each replay
__device__ int   g_ideg[NREL * NNODES];
__device__ float g_inorm[NREL * NNODES];
__device__ int   g_off[NNODES + 1];
__device__ int   g_cursor[NNODES];
__device__ __align__(128) int2 g_epack[NREL * NEDGE]; // {r*NPAD+src, bits(dst-norm)}
__device__ int   g_bsum[64];
__device__ int   g_bar;

// ---------------- fused: degree histograms (2x int4) + fp16 converts --------
#define DEG_B   ((NREL * E8 + 255) / 256)                    // 879
#define CONVX_B ((NPAD * (FIN1 / 8) + 255) / 256)            // 3128
#define CONVW_B ((NREL * (FIN1 + FHID) * FHID + 255) / 256)  // 144

__global__ void degconv_kernel(const float* __restrict__ x,
                               const float* __restrict__ W1, const float* __restrict__ W2,
                               const float* __restrict__ b1, const float* __restrict__ b2,
                               const int* __restrict__ src, const int* __restrict__ dst) {
    int b = blockIdx.x;
    if (b < DEG_B) {
        int t = b * 256 + threadIdx.x;
        if (t >= NREL * E8) return;
        int r = t / E8;
        int i = (t - r * E8) * 2;
        const int4* sp = (const int4*)(src + (size_t)r * NEDGE);
        const int4* dp = (const int4*)(dst + (size_t)r * NEDGE);
        int4 sa = sp[i], sb = sp[i + 1];
        int4 da = dp[i], db = dp[i + 1];
        int rb = r * NNODES;
        atomicAdd(&g_odeg[rb + sa.x], 1); atomicAdd(&g_odeg[rb + sa.y], 1);
        atomicAdd(&g_odeg[rb + sa.z], 1); atomicAdd(&g_odeg[rb + sa.w], 1);
        atomicAdd(&g_odeg[rb + sb.x], 1); atomicAdd(&g_odeg[rb + sb.y], 1);
        atomicAdd(&g_odeg[rb + sb.z], 1); atomicAdd(&g_odeg[rb + sb.w], 1);
        atomicAdd(&g_ideg[rb + da.x], 1); atomicAdd(&g_ideg[rb + da.y], 1);
        atomicAdd(&g_ideg[rb + da.z], 1); atomicAdd(&g_ideg[rb + da.w], 1);
        atomicAdd(&g_ideg[rb + db.x], 1); atomicAdd(&g_ideg[rb + db.y], 1);
        atomicAdd(&g_ideg[rb + db.z], 1); atomicAdd(&g_ideg[rb + db.w], 1);
    } else if (b < DEG_B + CONVX_B) {
        int i = (b - DEG_B) * 256 + threadIdx.x;
        if (i >= NPAD * (FIN1 / 8)) return;
        size_t gi = (size_t)i * 8;
        int row = (int)(gi >> 7);
        union { uint4 u; __half2 h[4]; } p;
        if (row < NNODES) {
            float4 a = *(const float4*)(x + gi);
            float4 c = *(const float4*)(x + gi + 4);
            p.h[0] = __floats2half2_rn(a.x, a.y);
            p.h[1] = __floats2half2_rn(a.z, a.w);
            p.h[2] = __floats2half2_rn(c.x, c.y);
            p.h[3] = __floats2half2_rn(c.z, c.w);
        } else {
            p.h[0] = p.h[1] = p.h[2] = p.h[3] = __floats2half2_rn(0.f, 0.f);
        }
        *(uint4*)(g_xh + gi) = p.u;
    } else {
        int i = (b - DEG_B - CONVX_B) * 256 + threadIdx.x;
        const int T1 = NREL * FIN1 * FHID;
        const int T2 = NREL * FHID * FHID;
        if (i < T1) g_w1h[i] = __float2half_rn(W1[i]);
        else if (i < T1 + T2) g_w2h[i - T1] = __float2half_rn(W2[i - T1]);
        if (b == DEG_B + CONVX_B && threadIdx.x < FHID) {
            int c = threadIdx.x;
            g_cb1[c] = b1[c] + b1[FHID + c] + b1[2 * FHID + c];
            g_cb2[c] = b2[c] + b2[FHID + c] + b2[2 * FHID + c];
        }
    }
}

// ---------------- single-launch CSR build: scan + apply + fill --------------
__device__ __forceinline__ void grid_barrier(int target) {
    __syncthreads();
    if (threadIdx.x == 0) {
        __threadfence();
        atomicAdd(&g_bar, 1);
        while (*(volatile int*)&g_bar < target) { }
        __threadfence();
    }
    __syncthreads();
}

__global__ void __launch_bounds__(256, 4)
csr_kernel(const int* __restrict__ src, const int* __restrict__ dst, int N) {
    const int t = threadIdx.x, bid = blockIdx.x;
    const int scanB = (N + 1023) / 1024;    // 49

    if (bid < scanB) {
        __shared__ int sh[256];
        int base = bid * 1024 + t * 4;
        int v[4];
        #pragma unroll
        for (int j = 0; j < 4; j++) {
            int n = base + j;
            v[j] = (n < N) ? (g_ideg[n] + g_ideg[N + n] + g_ideg[2 * N + n]) : 0;
        }
        int t0 = v[0], t1 = t0 + v[1], t2 = t1 + v[2], t3 = t2 + v[3];
        sh[t] = t3;
        __syncthreads();
        for (int off = 1; off < 256; off <<= 1) {
            int x = (t >= off) ? sh[t - off] : 0;
            __syncthreads();
            sh[t] += x;
            __syncthreads();
        }
        int excl = (t > 0) ? sh[t - 1] : 0;
        if (base + 0 < N) g_off[base + 0] = excl;
        if (base + 1 < N) g_off[base + 1] = excl + t0;
        if (base + 2 < N) g_off[base + 2] = excl + t1;
        if (base + 3 < N) g_off[base + 3] = excl + t2;
        if (t == 255) g_bsum[bid] = sh[255];
    }
    grid_barrier(CSR_GRID);

    __shared__ int pb[64];
    if (t == 0) {
        int s = 0;
        for (int i = 0; i < scanB; i++) { int v = g_bsum[i]; pb[i] = s; s += v; }
    }
    __syncthreads();
    for (int i = bid * 256 + t; i < N; i += CSR_GRID * 256) {
        int v = g_off[i] + pb[i >> 10];
        g_off[i] = v;
        g_cursor[i] = v;
    }
    for (int i = bid * 256 + t; i < NREL * N; i += CSR_GRID * 256) {
        int id = g_ideg[i];
        g_inorm[i] = rsqrtf((float)(id < 1 ? 1 : id));
    }
    if (bid == 0 && t == 0) g_off[N] = NREL * NEDGE;
    grid_barrier(2 * CSR_GRID);

    for (int g = bid * 256 + t; g < NREL * E4; g += CSR_GRID * 256) {
        int r = g / E4;
        int i = g - r * E4;
        int4 s4 = ((const int4*)(src + (size_t)r * NEDGE))[i];
        int4 d4 = ((const int4*)(dst + (size_t)r * NEDGE))[i];
        int rn = r * NNODES, rp = r * NPAD;
        float w0 = g_inorm[rn + d4.x];
        float w1 = g_inorm[rn + d4.y];
        float w2 = g_inorm[rn + d4.z];
        float w3 = g_inorm[rn + d4.w];
        int p0 = atomicAdd(&g_cursor[d4.x], 1);
        int p1 = atomicAdd(&g_cursor[d4.y], 1);
        int p2 = atomicAdd(&g_cursor[d4.z], 1);
        int p3 = atomicAdd(&g_cursor[d4.w], 1);
        g_epack[p0] = make_int2(rp + s4.x, __float_as_int(w0));
        g_epack[p1] = make_int2(rp + s4.y, __float_as_int(w1));
        g_epack[p2] = make_int2(rp + s4.z, __float_as_int(w2));
        g_epack[p3] = make_int2(rp + s4.w, __float_as_int(w3));
    }
}

// ---------------- smem-staged tensor-core GEMM ------------------------------
template <int K>
__global__ void __launch_bounds__(256)
gemm_tc(const __half* __restrict__ Xh, const __half* __restrict__ Wh,
        __half* __restrict__ Hout, int N) {
    constexpr int AS = K + 8;
    constexpr int SBYTES = 64 * AS * 2 + K * 72 * 2;
    __shared__ __align__(16) unsigned char sbuf[SBYTES];
    __half* sA = (__half*)sbuf;
    __half* sB = (__half*)(sbuf + (size_t)64 * AS * 2);
    float*  sC = (float*)sbuf;

    const int r    = blockIdx.y;
    const int row0 = blockIdx.x * 64;
    const int tid  = threadIdx.x;
    const int wid  = tid >> 5;
    const int mt   = wid >> 1;
    const int nh   = (wid & 1) * 32;

    #pragma unroll
    for (int i = tid; i < 64 * (K / 8); i += 256) {
        int row = i / (K / 8), c8 = i % (K / 8);
        uint4 v = *(const uint4*)(Xh + (size_t)(row0 + row) * K + c8 * 8);
        *(uint4*)(sA + row * AS + c8 * 8) = v;
    }
    #pragma unroll
    for (int i = tid; i < K * 8; i += 256) {
        int row = i >> 3, c8 = i & 7;
        uint4 v = *(const uint4*)(Wh + (size_t)r * K * 64 + row * 64 + c8 * 8);
        *(uint4*)(sB + row * 72 + c8 * 8) = v;
    }
    __syncthreads();

    wmma::fragment<wmma::accumulator, 16, 16, 16, float> c0, c1;
    wmma::fill_fragment(c0, 0.0f);
    wmma::fill_fragment(c1, 0.0f);
    #pragma unroll
    for (int k0 = 0; k0 < K; k0 += 16) {
        wmma::fragment<wmma::matrix_a, 16, 16, 16, __half, wmma::row_major> a;
        wmma::fragment<wmma::matrix_b, 16, 16, 16, __half, wmma::row_major> b0, b1;
        wmma::load_matrix_sync(a, sA + mt * 16 * AS + k0, AS);
        wmma::load_matrix_sync(b0, sB + k0 * 72 + nh, 72);
        wmma::load_matrix_sync(b1, sB + k0 * 72 + nh + 16, 72);
        wmma::mma_sync(c0, a, b0, c0);
        wmma::mma_sync(c1, a, b1, c1);
    }
    __syncthreads();
    wmma::store_matrix_sync(sC + mt * 16 * 72 + nh, c0, 72, wmma::mem_row_major);
    wmma::store_matrix_sync(sC + mt * 16 * 72 + nh + 16, c1, 72, wmma::mem_row_major);
    __syncthreads();

    #pragma unroll
    for (int i = tid; i < 64 * 32; i += 256) {
        int row = i >> 5, c2 = i & 31;
        int grow = row0 + row;
        if (grow < N) {
            int od = g_odeg[r * N + grow];
            float s = rsqrtf((float)(od < 1 ? 1 : od));
            float v0 = sC[row * 72 + c2 * 2];
            float v1 = sC[row * 72 + c2 * 2 + 1];
            ((__half2*)Hout)[((size_t)r * NPAD + grow) * 32 + c2] =
                __floats2half2_rn(v0 * s, v1 * s);
        }
    }
}

// ---------------- gather: 16 edges/warp-iter (4 loads in flight per lane) ---
// lanes in 4 groups of 8; lane handles 8 channels (one uint4 of halves).
// CLEANUP=true (layer 2): tail also re-zeroes degree counters for next replay.
template <bool HALF_OUT, bool CLEANUP>
__global__ void gather_kernel(const __half* __restrict__ H, const float* __restrict__ cb,
                              void* __restrict__ outp, int N) {
    int warp = (blockIdx.x * blockDim.x + threadIdx.x) >> 5;
    int lane = threadIdx.x & 31;
    if (warp >= N) return;
    const int n = warp;
    const int g = lane >> 3, s = lane & 7;

    const uint4* Hv = (const uint4*)H;   // row = 8 uint4
    int beg = g_off[n];
    int end = g_off[n + 1];

    float acc[8] = {};
    for (int base = beg; base < end; base += 32) {
        int m = end - base; if (m > 32) m = 32;
        int   myid = 0;
        float mywt = 0.f;
        if (lane < m) {
            int2 pk = g_epack[base + lane];
            myid = pk.x;
            mywt = __int_as_float(pk.y);
        }
        int jmax = (m + 15) >> 4;
        for (int j = 0; j < jmax; j++) {
            int e0 = j * 16 + g;
            int   id0 = __shfl_sync(0xffffffffu, myid, e0);
            float wt0 = __shfl_sync(0xffffffffu, mywt, e0);
            int   id1 = __shfl_sync(0xffffffffu, myid, e0 + 4);
            float wt1 = __shfl_sync(0xffffffffu, mywt, e0 + 4);
            int   id2 = __shfl_sync(0xffffffffu, myid, e0 + 8);
            float wt2 = __shfl_sync(0xffffffffu, mywt, e0 + 8);
            int   id3 = __shfl_sync(0xffffffffu, myid, e0 + 12);
            float wt3 = __shfl_sync(0xffffffffu, mywt, e0 + 12);
            uint4 hv0 = Hv[(size_t)id0 * 8 + s];
            uint4 hv1 = Hv[(size_t)id1 * 8 + s];
            uint4 hv2 = Hv[(size_t)id2 * 8 + s];
            uint4 hv3 = Hv[(size_t)id3 * 8 + s];
            union { uint4 u; __half2 h[4]; } p0, p1, p2, p3;
            p0.u = hv0; p1.u = hv1; p2.u = hv2; p3.u = hv3;
            #pragma unroll
            for (int k = 0; k < 4; k++) {
                float2 f0 = __half22float2(p0.h[k]);
                float2 f1 = __half22float2(p1.h[k]);
                float2 f2 = __half22float2(p2.h[k]);
                float2 f3 = __half22float2(p3.h[k]);
                acc[2 * k]     += wt0 * f0.x + wt1 * f1.x + wt2 * f2.x + wt3 * f3.x;
                acc[2 * k + 1] += wt0 * f0.y + wt1 * f1.y + wt2 * f2.y + wt3 * f3.y;
            }
        }
    }

    #pragma unroll
    for (int off = 8; off < 32; off <<= 1) {
        #pragma unroll
        for (int k = 0; k < 8; k++)
            acc[k] += __shfl_xor_sync(0xffffffffu, acc[k], off);
    }

    if (lane < 8) {
        int c = lane * 8;
        #pragma unroll
        for (int k = 0; k < 8; k++) acc[k] += cb[c + k];
        if (HALF_OUT) {
            #pragma unroll
            for (int k = 0; k < 8; k++) acc[k] = fmaxf(acc[k], 0.f);
            union { uint4 u; __half2 h[4]; } p;
            p.h[0] = __floats2half2_rn(acc[0], acc[1]);
            p.h[1] = __floats2half2_rn(acc[2], acc[3]);
            p.h[2] = __floats2half2_rn(acc[4], acc[5]);
            p.h[3] = __floats2half2_rn(acc[6], acc[7]);
            *(uint4*)((__half*)outp + (size_t)n * 64 + c) = p.u;
        } else {
            float* o = (float*)outp + (size_t)n * 64 + c;
            *(float4*)o       = make_float4(acc[0], acc[1], acc[2], acc[3]);
            *(float4*)(o + 4) = make_float4(acc[4], acc[5], acc[6], acc[7]);
        }
    }
    if (CLEANUP) {
        if (lane >= 8 && lane < 11) g_odeg[(lane - 8) * N + n] = 0;
        if (lane >= 11 && lane < 14) g_ideg[(lane - 11) * N + n] = 0;
        if (n == 0 && lane == 14) g_bar = 0;
    }
}

// ---------------- launch ----------------
extern "C" void kernel_launch(void* const* d_in, const int* in_sizes, int n_in,
                              void* d_out, int out_size) {
    const float* x   = (const float*)d_in[0];
    const float* W1  = (const float*)d_in[1];
    const float* b1  = (const float*)d_in[2];
    const float* W2  = (const float*)d_in[3];
    const float* b2  = (const float*)d_in[4];
    const int*   src = (const int*)d_in[5];
    const int*   dst = (const int*)d_in[6];
    float* out = (float*)d_out;

    const int N = in_sizes[0] / FIN1;   // 50000

    __half *Hp, *xh, *w1h, *w2h, *h1h;
    float *cb1, *cb2;
    cudaGetSymbolAddress((void**)&Hp,  g_H);
    cudaGetSymbolAddress((void**)&xh,  g_xh);
    cudaGetSymbolAddress((void**)&w1h, g_w1h);
    cudaGetSymbolAddress((void**)&w2h, g_w2h);
    cudaGetSymbolAddress((void**)&h1h, g_h1h);
    cudaGetSymbolAddress((void**)&cb1, g_cb1);
    cudaGetSymbolAddress((void**)&cb2, g_cb2);

    dim3 gemm_grid(NPAD / 64, NREL);
    int gather_blocks = (N * 32 + 255) / 256;

    degconv_kernel<<<DEG_B + CONVX_B + CONVW_B, 256>>>(x, W1, W2, b1, b2, src, dst);
    csr_kernel<<<CSR_GRID, 256>>>(src, dst, N);
    gemm_tc<FIN1><<<gemm_grid, 256>>>(xh, w1h, Hp, N);
    gather_kernel<true, false><<<gather_blocks, 256>>>(Hp, cb1, h1h, N);
    gemm_tc<FHID><<<gemm_grid, 256>>>(h1h, w2h, Hp, N);
    gather_kernel<false, true><<<gather_blocks, 256>>>(Hp, cb2, out, N);
}